// round 6
// baseline (speedup 1.0000x reference)
#include <cuda_runtime.h>
#include <math.h>
#include <stdint.h>

#define SN    255
#define B_    64
#define EMB   200
#define HID   300
#define NROWS (SN * B_)     // 16320
#define NC    1200
#define KCH_E 13            // ceil(200/16)
#define KCH_U 19            // ceil(300/16)
#define NBG0  160           // gemm0 B fragment groups (1280 padded cols)
#define NBGI  128           // U_iou groups (1024 padded cols, N=900)
#define NBGF  48            // U_f groups (384 padded cols, N=300)

// ---- device scratch ----
__device__ float g_wx[NROWS * NC];
__device__ float g_H [NROWS * HID];
__device__ float g_C [NROWS * HID];
__device__ float g_Ti[64 * B_ * 900];    // iou GEMM out (parents, max np=64)
__device__ float g_Tf[128 * B_ * 300];   // f GEMM out (children, max nc=128)
// B matrices pre-packed in mma-fragment order (tf32):
// entry ((nbg*KCH + kch)*32 + ln) = { B[n][k+tk], B[n][k+tk+4], B[n][k+8+tk], B[n][k+12+tk] }
// n = nbg*8 + (ln>>2), tk = ln&3, k = kch*16.
__device__ uint4 g_Bw_f[NBG0 * KCH_E * 32];
__device__ uint4 g_Bi_f[NBGI * KCH_U * 32];
__device__ uint4 g_Bf_f[NBGF * KCH_U * 32];
__device__ float g_bias[NC];

__device__ __forceinline__ float sigmoidf(float x) { return 1.0f / (1.0f + expf(-x)); }
__device__ __forceinline__ uint32_t f2tf(float x) {
    uint32_t u; asm("cvt.rna.tf32.f32 %0, %1;" : "=r"(u) : "f"(x)); return u;
}

// ---------------------------------------------------------------------------
// Prep: pack the three B matrices into fragment order + concat bias.
// ---------------------------------------------------------------------------
__global__ void prep_kernel(const float* __restrict__ W_iou, const float* __restrict__ W_f,
                            const float* __restrict__ U_iou, const float* __restrict__ U_f,
                            const float* __restrict__ b_iou, const float* __restrict__ b_f)
{
    int idx = blockIdx.x * blockDim.x + threadIdx.x;

    if (idx < NBG0 * KCH_E * 32) {
        int ln = idx & 31, kch = (idx >> 5) % KCH_E, nbg = idx / (32 * KCH_E);
        int n = nbg * 8 + (ln >> 2), tk = ln & 3, kb = kch * 16;
        uint4 v; uint32_t* vp = (uint32_t*)&v;
        #pragma unroll
        for (int q = 0; q < 4; ++q) {
            int k = kb + (q & 1) * 4 + (q >> 1) * 8 + tk;
            float f = 0.0f;
            if (k < EMB && n < NC)
                f = (n < 900) ? W_iou[k * 900 + n] : W_f[k * 300 + (n - 900)];
            vp[q] = f2tf(f);
        }
        g_Bw_f[idx] = v;
    }
    if (idx < NBGI * KCH_U * 32) {
        int ln = idx & 31, kch = (idx >> 5) % KCH_U, nbg = idx / (32 * KCH_U);
        int n = nbg * 8 + (ln >> 2), tk = ln & 3, kb = kch * 16;
        uint4 v; uint32_t* vp = (uint32_t*)&v;
        #pragma unroll
        for (int q = 0; q < 4; ++q) {
            int k = kb + (q & 1) * 4 + (q >> 1) * 8 + tk;
            float f = (k < HID && n < 900) ? U_iou[k * 900 + n] : 0.0f;
            vp[q] = f2tf(f);
        }
        g_Bi_f[idx] = v;
    }
    if (idx < NBGF * KCH_U * 32) {
        int ln = idx & 31, kch = (idx >> 5) % KCH_U, nbg = idx / (32 * KCH_U);
        int n = nbg * 8 + (ln >> 2), tk = ln & 3, kb = kch * 16;
        uint4 v; uint32_t* vp = (uint32_t*)&v;
        #pragma unroll
        for (int q = 0; q < 4; ++q) {
            int k = kb + (q & 1) * 4 + (q >> 1) * 8 + tk;
            float f = (k < HID && n < 300) ? U_f[k * 300 + n] : 0.0f;
            vp[q] = f2tf(f);
        }
        g_Bf_f[idx] = v;
    }
    if (idx < NC) g_bias[idx] = (idx < 900) ? b_iou[idx] : b_f[idx - 900];
}

// ---- cp.async helpers ----
#define CPA16(dst, src)                                                     \
    asm volatile("cp.async.ca.shared.global [%0], [%1], 16;"                \
                 :: "r"(dst), "l"(src))
#define CPA16Z(dst, src, sz)                                                \
    asm volatile("cp.async.ca.shared.global [%0], [%1], 16, %2;"            \
                 :: "r"(dst), "l"(src), "r"(sz))
#define CPCOMMIT() asm volatile("cp.async.commit_group;")
#define CPWAIT(n)  asm volatile("cp.async.wait_group %0;" :: "n"(n))

// ---------------------------------------------------------------------------
// gemm_wx: wx = [emb@W_iou+b_iou | emb@W_f+b_f], M=16320, K=200, N=1200.
// 3-stage cp.async, 1 sync/iter. Block 128x128, 256 thr, warp 32x64.
// ---------------------------------------------------------------------------
__global__ __launch_bounds__(256, 2) void gemm_wx(
    const float* __restrict__ embedTab, const int* __restrict__ xg)
{
    __shared__ __align__(16) float As[3][128][20];
    __shared__ __align__(16) uint4 Bs[3][16][32];
    __shared__ const float* arows[128];

    const int tid = threadIdx.x;
    const int rowBase = blockIdx.x * 128;
    const int colBase = blockIdx.y * 128;

    if (tid < 128) {
        int m = rowBase + tid;
        int mc = (m < NROWS) ? m : (NROWS - 1);
        arows[tid] = embedTab + (size_t)xg[mc] * EMB;
    }
    __syncthreads();

    const int lane = tid & 31, warp = tid >> 5;
    const int wm = (warp & 3) * 32, wn = (warp >> 2) * 64;
    const int nbW = wn >> 3;
    const int tg = lane >> 2, tk = lane & 3;
    const int nbgBase = colBase >> 3;

    float acc[2][8][4] = {};

#define FILL_WX(ST, KC)                                                         \
    do {                                                                        \
        int _k0 = (KC) * 16;                                                    \
        _Pragma("unroll")                                                       \
        for (int _i = 0; _i < 2; ++_i) {                                        \
            int _e = tid + _i * 256, _r = _e >> 2, _c = _e & 3;                 \
            uint32_t _d = (uint32_t)__cvta_generic_to_shared(&As[ST][_r][_c*4]);\
            const float* _s = arows[_r] + _k0 + _c * 4;                         \
            int _vb = EMB - (_k0 + _c * 4);                                     \
            int _sz = (_vb >= 4) ? 16 : ((_vb > 0) ? _vb * 4 : 0);              \
            CPA16Z(_d, _s, _sz);                                                \
        }                                                                       \
        _Pragma("unroll")                                                       \
        for (int _i = 0; _i < 2; ++_i) {                                        \
            int _e = tid + _i * 256, _nb = _e >> 5, _ln = _e & 31;              \
            uint32_t _d = (uint32_t)__cvta_generic_to_shared(&Bs[ST][_nb][_ln]);\
            const uint4* _s = g_Bw_f + ((size_t)(nbgBase + _nb) * KCH_E + (KC)) * 32 + _ln; \
            CPA16(_d, _s);                                                      \
        }                                                                       \
        CPCOMMIT();                                                             \
    } while (0)

    FILL_WX(0, 0);
    FILL_WX(1, 1);

    for (int kch = 0; kch < KCH_E; ++kch) {
        const int s = kch % 3;
        if (kch + 1 < KCH_E) { CPWAIT(1); } else { CPWAIT(0); }
        __syncthreads();
        if (kch + 2 < KCH_E) {
            FILL_WX((kch + 2) % 3, kch + 2);
        }

        uint32_t a[2][2][4];
        #pragma unroll
        for (int kb = 0; kb < 2; ++kb)
            #pragma unroll
            for (int mf = 0; mf < 2; ++mf) {
                int r = wm + mf * 16 + tg;
                a[kb][mf][0] = __float_as_uint(As[s][r    ][kb * 8 + tk]);
                a[kb][mf][1] = __float_as_uint(As[s][r + 8][kb * 8 + tk]);
                a[kb][mf][2] = __float_as_uint(As[s][r    ][kb * 8 + tk + 4]);
                a[kb][mf][3] = __float_as_uint(As[s][r + 8][kb * 8 + tk + 4]);
            }
        #pragma unroll
        for (int nf = 0; nf < 8; ++nf) {
            uint4 bq = Bs[s][nbW + nf][lane];
            #pragma unroll
            for (int mf = 0; mf < 2; ++mf) {
                asm("mma.sync.aligned.m16n8k8.row.col.f32.tf32.tf32.f32 "
                    "{%0,%1,%2,%3},{%4,%5,%6,%7},{%8,%9},{%0,%1,%2,%3};"
                    : "+f"(acc[mf][nf][0]), "+f"(acc[mf][nf][1]),
                      "+f"(acc[mf][nf][2]), "+f"(acc[mf][nf][3])
                    : "r"(a[0][mf][0]), "r"(a[0][mf][1]), "r"(a[0][mf][2]), "r"(a[0][mf][3]),
                      "r"(bq.x), "r"(bq.y));
                asm("mma.sync.aligned.m16n8k8.row.col.f32.tf32.tf32.f32 "
                    "{%0,%1,%2,%3},{%4,%5,%6,%7},{%8,%9},{%0,%1,%2,%3};"
                    : "+f"(acc[mf][nf][0]), "+f"(acc[mf][nf][1]),
                      "+f"(acc[mf][nf][2]), "+f"(acc[mf][nf][3])
                    : "r"(a[1][mf][0]), "r"(a[1][mf][1]), "r"(a[1][mf][2]), "r"(a[1][mf][3]),
                      "r"(bq.z), "r"(bq.w));
            }
        }
    }
#undef FILL_WX

    #pragma unroll
    for (int mf = 0; mf < 2; ++mf)
        #pragma unroll
        for (int nf = 0; nf < 8; ++nf) {
            int row = rowBase + wm + mf * 16 + tg;
            int col = colBase + wn + nf * 8 + tk * 2;
            if (col < NC) {
                float b0 = g_bias[col], b1 = g_bias[col + 1];
                if (row < NROWS)
                    *(float2*)(g_wx + (size_t)row * NC + col) =
                        make_float2(acc[mf][nf][0] + b0, acc[mf][nf][1] + b1);
                if (row + 8 < NROWS)
                    *(float2*)(g_wx + (size_t)(row + 8) * NC + col) =
                        make_float2(acc[mf][nf][2] + b0, acc[mf][nf][3] + b1);
            }
        }
}

// ---------------------------------------------------------------------------
// level_gemm: fused per-level GEMMs.
//  blockIdx.y < 8 : IOU: A = H[2p+1]+H[2p+2] (dual slabs), B=U_iou, N=900,
//                   M = np*64 -> g_Ti
//  blockIdx.y >= 8: F:   A = H[child],        B=U_f,   N=300,
//                   M = np*128 -> g_Tf
// ---------------------------------------------------------------------------
__global__ __launch_bounds__(256, 2) void level_gemm(int p0, int np)
{
    __shared__ __align__(16) float AsL[3][128][20];
    __shared__ __align__(16) float AsR[3][128][20];
    __shared__ __align__(16) uint4 Bs[3][16][32];
    __shared__ const float* rowL[128];
    __shared__ const float* rowR[128];

    const int tid = threadIdx.x;
    const bool isF = (blockIdx.y >= 8);
    const int Mrows = isF ? np * 128 : np * 64;
    const int rowBase = blockIdx.x * 128;
    if (rowBase >= Mrows) return;
    const int colBase = (isF ? (blockIdx.y - 8) : blockIdx.y) * 128;

    if (tid < 128) {
        int m = rowBase + tid;
        int mc = (m < Mrows) ? m : (Mrows - 1);
        int b = mc & 63, i = mc >> 6;
        if (isF) {
            int c = 2 * p0 + 1 + i;
            rowL[tid] = g_H + (size_t)(c * B_ + b) * HID;
        } else {
            int p = p0 + i;
            rowL[tid] = g_H + (size_t)((2 * p + 1) * B_ + b) * HID;
            rowR[tid] = g_H + (size_t)((2 * p + 2) * B_ + b) * HID;
        }
    }
    __syncthreads();

    const int lane = tid & 31, warp = tid >> 5;
    const int wm = (warp & 3) * 32, wn = (warp >> 2) * 64;
    const int nbW = wn >> 3;
    const int tg = lane >> 2, tk = lane & 3;
    const int nbgBase = colBase >> 3;
    const uint4* gB = isF ? g_Bf_f : g_Bi_f;

    float acc[2][8][4] = {};

#define FILL_LV(ST, KC)                                                         \
    do {                                                                        \
        int _k0 = (KC) * 16;                                                    \
        _Pragma("unroll")                                                       \
        for (int _i = 0; _i < 2; ++_i) {                                        \
            int _e = tid + _i * 256, _r = _e >> 2, _c = _e & 3;                 \
            int _vb = HID - (_k0 + _c * 4);                                     \
            int _sz = (_vb >= 4) ? 16 : ((_vb > 0) ? _vb * 4 : 0);              \
            uint32_t _d = (uint32_t)__cvta_generic_to_shared(&AsL[ST][_r][_c*4]);\
            CPA16Z(_d, rowL[_r] + _k0 + _c * 4, _sz);                           \
            if (!isF) {                                                         \
                uint32_t _d2 = (uint32_t)__cvta_generic_to_shared(&AsR[ST][_r][_c*4]);\
                CPA16Z(_d2, rowR[_r] + _k0 + _c * 4, _sz);                      \
            }                                                                   \
        }                                                                       \
        _Pragma("unroll")                                                       \
        for (int _i = 0; _i < 2; ++_i) {                                        \
            int _e = tid + _i * 256, _nb = _e >> 5, _ln = _e & 31;              \
            uint32_t _d = (uint32_t)__cvta_generic_to_shared(&Bs[ST][_nb][_ln]);\
            const uint4* _s = gB + ((size_t)(nbgBase + _nb) * KCH_U + (KC)) * 32 + _ln; \
            CPA16(_d, _s);                                                      \
        }                                                                       \
        CPCOMMIT();                                                             \
    } while (0)

    FILL_LV(0, 0);
    FILL_LV(1, 1);

    for (int kch = 0; kch < KCH_U; ++kch) {
        const int s = kch % 3;
        if (kch + 1 < KCH_U) { CPWAIT(1); } else { CPWAIT(0); }
        __syncthreads();
        if (kch + 2 < KCH_U) {
            FILL_LV((kch + 2) % 3, kch + 2);
        }

        uint32_t a[2][2][4];
        #pragma unroll
        for (int kb = 0; kb < 2; ++kb)
            #pragma unroll
            for (int mf = 0; mf < 2; ++mf) {
                int r = wm + mf * 16 + tg;
                float v0 = AsL[s][r    ][kb * 8 + tk];
                float v1 = AsL[s][r + 8][kb * 8 + tk];
                float v2 = AsL[s][r    ][kb * 8 + tk + 4];
                float v3 = AsL[s][r + 8][kb * 8 + tk + 4];
                if (!isF) {
                    v0 += AsR[s][r    ][kb * 8 + tk];
                    v1 += AsR[s][r + 8][kb * 8 + tk];
                    v2 += AsR[s][r    ][kb * 8 + tk + 4];
                    v3 += AsR[s][r + 8][kb * 8 + tk + 4];
                }
                a[kb][mf][0] = __float_as_uint(v0);
                a[kb][mf][1] = __float_as_uint(v1);
                a[kb][mf][2] = __float_as_uint(v2);
                a[kb][mf][3] = __float_as_uint(v3);
            }
        #pragma unroll
        for (int nf = 0; nf < 8; ++nf) {
            uint4 bq = Bs[s][nbW + nf][lane];
            #pragma unroll
            for (int mf = 0; mf < 2; ++mf) {
                asm("mma.sync.aligned.m16n8k8.row.col.f32.tf32.tf32.f32 "
                    "{%0,%1,%2,%3},{%4,%5,%6,%7},{%8,%9},{%0,%1,%2,%3};"
                    : "+f"(acc[mf][nf][0]), "+f"(acc[mf][nf][1]),
                      "+f"(acc[mf][nf][2]), "+f"(acc[mf][nf][3])
                    : "r"(a[0][mf][0]), "r"(a[0][mf][1]), "r"(a[0][mf][2]), "r"(a[0][mf][3]),
                      "r"(bq.x), "r"(bq.y));
                asm("mma.sync.aligned.m16n8k8.row.col.f32.tf32.tf32.f32 "
                    "{%0,%1,%2,%3},{%4,%5,%6,%7},{%8,%9},{%0,%1,%2,%3};"
                    : "+f"(acc[mf][nf][0]), "+f"(acc[mf][nf][1]),
                      "+f"(acc[mf][nf][2]), "+f"(acc[mf][nf][3])
                    : "r"(a[1][mf][0]), "r"(a[1][mf][1]), "r"(a[1][mf][2]), "r"(a[1][mf][3]),
                      "r"(bq.z), "r"(bq.w));
            }
        }
    }
#undef FILL_LV

    const int NOUT = isF ? 300 : 900;
    float* Cout = isF ? g_Tf : g_Ti;
    #pragma unroll
    for (int mf = 0; mf < 2; ++mf)
        #pragma unroll
        for (int nf = 0; nf < 8; ++nf) {
            int row = rowBase + wm + mf * 16 + tg;
            int col = colBase + wn + nf * 8 + tk * 2;
            if (col < NOUT) {
                if (row < Mrows)
                    *(float2*)(Cout + (size_t)row * NOUT + col) =
                        make_float2(acc[mf][nf][0], acc[mf][nf][1]);
                if (row + 8 < Mrows)
                    *(float2*)(Cout + (size_t)(row + 8) * NOUT + col) =
                        make_float2(acc[mf][nf][2], acc[mf][nf][3]);
            }
        }
}

// ---------------------------------------------------------------------------
// Leaves (nodes 127..254)
// ---------------------------------------------------------------------------
__global__ void leaf_kernel()
{
    int idx = blockIdx.x * blockDim.x + threadIdx.x;
    if (idx >= 128 * B_ * HID) return;
    int n = idx % HID;
    int r = idx / HID;
    int row = 127 * B_ + r;
    const float* wx = g_wx + (size_t)row * NC;
    float iv = sigmoidf(wx[n]);
    float ov = sigmoidf(wx[300 + n]);
    float uv = tanhf(wx[600 + n]);
    float c = iv * uv;
    g_C[(size_t)row * HID + n] = c;
    g_H[(size_t)row * HID + n] = ov * tanhf(c);
}

// ---------------------------------------------------------------------------
// Per-level combine
// ---------------------------------------------------------------------------
__global__ void level_pw(int p0, int np)
{
    int idx = blockIdx.x * blockDim.x + threadIdx.x;
    int tot = np * B_ * HID;
    if (idx >= tot) return;
    int n  = idx % HID;
    int r  = idx / HID;      // pi*64 + b
    int b  = r % B_;
    int pi = r / B_;
    int p  = p0 + pi;

    const float* wx = g_wx + (size_t)(p * B_ + b) * NC;
    const float* ti = g_Ti + (size_t)r * 900;

    float iv = sigmoidf(wx[n]       + ti[n]);
    float ov = sigmoidf(wx[300 + n] + ti[300 + n]);
    float uv = tanhf   (wx[600 + n] + ti[600 + n]);
    float wf = wx[900 + n];
    float fl = sigmoidf(wf + g_Tf[(size_t)((2 * pi    ) * B_ + b) * 300 + n]);
    float fr = sigmoidf(wf + g_Tf[(size_t)((2 * pi + 1) * B_ + b) * 300 + n]);

    int lc = 2 * p + 1, rc = 2 * p + 2;
    float fc = fl * g_C[(size_t)(lc * B_ + b) * HID + n]
             + fr * g_C[(size_t)(rc * B_ + b) * HID + n];
    float c = iv * uv + fc;
    float h = ov * tanhf(c);
    g_C[(size_t)(p * B_ + b) * HID + n] = c;
    g_H[(size_t)(p * B_ + b) * HID + n] = h;
}

// ---------------------------------------------------------------------------
// Output head
// ---------------------------------------------------------------------------
__global__ __launch_bounds__(64) void out_kernel(
    const float* __restrict__ W_out, const float* __restrict__ b_out,
    float* __restrict__ out)
{
    const int b = threadIdx.x;
    const float* h = g_H + (size_t)b * HID;
    float l0 = b_out[0], l1 = b_out[1];
    #pragma unroll 4
    for (int k = 0; k < HID; ++k) {
        float hv = h[k];
        l0 = fmaf(hv, W_out[k * 2 + 0], l0);
        l1 = fmaf(hv, W_out[k * 2 + 1], l1);
    }
    float m   = fmaxf(l0, l1);
    float lse = m + logf(expf(l0 - m) + expf(l1 - m));
    out[b * 2 + 0] = l0 - lse;
    out[b * 2 + 1] = l1 - lse;
}

// ---------------------------------------------------------------------------
extern "C" void kernel_launch(void* const* d_in, const int* in_sizes, int n_in,
                              void* d_out, int out_size)
{
    (void)in_sizes; (void)n_in; (void)out_size;
    const int*   x     = (const int*)  d_in[0];
    const float* embed = (const float*)d_in[3];
    const float* W_iou = (const float*)d_in[4];
    const float* U_iou = (const float*)d_in[5];
    const float* b_iou = (const float*)d_in[6];
    const float* W_f   = (const float*)d_in[7];
    const float* U_f   = (const float*)d_in[8];
    const float* b_f   = (const float*)d_in[9];
    const float* W_out = (const float*)d_in[10];
    const float* b_out = (const float*)d_in[11];

    prep_kernel<<<(NBGI * KCH_U * 32 + 255) / 256, 256>>>(W_iou, W_f, U_iou, U_f, b_iou, b_f);

    gemm_wx<<<dim3(128, 10), 256>>>(embed, x);
    leaf_kernel<<<(128 * B_ * HID + 255) / 256, 256>>>();

    for (int d = 6; d >= 0; --d) {
        int np = 1 << d;
        int p0 = np - 1;
        level_gemm<<<dim3(np, 11), 256>>>(p0, np);
        level_pw<<<(np * B_ * HID + 255) / 256, 256>>>(p0, np);
    }

    out_kernel<<<1, 64>>>(W_out, b_out, (float*)d_out);
}

// round 8
// speedup vs baseline: 1.0956x; 1.0956x over previous
#include <cuda_runtime.h>
#include <math.h>
#include <stdint.h>

#define SN    255
#define B_    64
#define EMB   200
#define HID   300
#define NROWS (SN * B_)     // 16320
#define NC    1200
#define H_LD  304           // padded fp32 row stride for H / Hsum
#define KCH_E 13            // ceil(200/16)
#define KCH_U 19            // ceil(300/16)
#define NBG0  160           // wx B groups  (1280 padded cols)
#define NBGI  128           // U_iou groups (1024 padded cols, N=900)
#define NBGF  48            // U_f groups   (384 padded cols,  N=300)

// ---- device scratch (device globals are zero-initialized at load) ----
__device__ float g_wx[NROWS * NC];
__device__ float g_H [NROWS * H_LD + 64];     // H, padded rows (cols 300..303 stay 0)
__device__ float g_Hs[64 * B_ * H_LD + 64];   // h_sum rows (parents of one level)
__device__ float g_C [NROWS * HID];
__device__ float g_Ti[64 * B_ * 900];         // iou GEMM out (parents)
__device__ float g_Tf[128 * B_ * 300];        // f GEMM out (children)
// B pre-packed tf32 fragments: entry ((nbg*KCH + kch)*32 + ln) =
//   { B[n][k+tk], B[n][k+tk+4], B[n][k+8+tk], B[n][k+12+tk] },
//   n = nbg*8 + (ln>>2), tk = ln&3, k = kch*16.
__device__ uint4 g_Bw_f[NBG0 * KCH_E * 32];
__device__ uint4 g_Bi_f[NBGI * KCH_U * 32];
__device__ uint4 g_Bf_f[NBGF * KCH_U * 32];
__device__ float g_bias[NC];

__device__ __forceinline__ float sigmoidf(float x) { return 1.0f / (1.0f + expf(-x)); }
__device__ __forceinline__ uint32_t f2tf(float x) {
    uint32_t u; asm("cvt.rna.tf32.f32 %0, %1;" : "=r"(u) : "f"(x)); return u;
}

// ---- cp.async helpers ----
#define CPA16(dst, src) \
    asm volatile("cp.async.ca.shared.global [%0], [%1], 16;" :: "r"(dst), "l"(src))
#define CPA16Z(dst, src, sz) \
    asm volatile("cp.async.ca.shared.global [%0], [%1], 16, %2;" :: "r"(dst), "l"(src), "r"(sz))
#define CPCOMMIT() asm volatile("cp.async.commit_group;")
#define CPWAIT(n)  asm volatile("cp.async.wait_group %0;" :: "n"(n))

// ---------------------------------------------------------------------------
// Prep: pack the three B matrices into tf32 fragment order + concat bias.
// ---------------------------------------------------------------------------
__global__ void prep_kernel(const float* __restrict__ W_iou, const float* __restrict__ W_f,
                            const float* __restrict__ U_iou, const float* __restrict__ U_f,
                            const float* __restrict__ b_iou, const float* __restrict__ b_f)
{
    int idx = blockIdx.x * blockDim.x + threadIdx.x;

    if (idx < NBG0 * KCH_E * 32) {
        int ln = idx & 31, kch = (idx >> 5) % KCH_E, nbg = idx / (32 * KCH_E);
        int n = nbg * 8 + (ln >> 2), tk = ln & 3, kb = kch * 16;
        uint4 v; uint32_t* vp = (uint32_t*)&v;
        #pragma unroll
        for (int q = 0; q < 4; ++q) {
            int k = kb + q * 4 + tk;
            float f = 0.0f;
            if (k < EMB && n < NC)
                f = (n < 900) ? W_iou[k * 900 + n] : W_f[k * 300 + (n - 900)];
            vp[q] = f2tf(f);
        }
        g_Bw_f[idx] = v;
    }
    if (idx < NBGI * KCH_U * 32) {
        int ln = idx & 31, kch = (idx >> 5) % KCH_U, nbg = idx / (32 * KCH_U);
        int n = nbg * 8 + (ln >> 2), tk = ln & 3, kb = kch * 16;
        uint4 v; uint32_t* vp = (uint32_t*)&v;
        #pragma unroll
        for (int q = 0; q < 4; ++q) {
            int k = kb + q * 4 + tk;
            float f = (k < HID && n < 900) ? U_iou[k * 900 + n] : 0.0f;
            vp[q] = f2tf(f);
        }
        g_Bi_f[idx] = v;
    }
    if (idx < NBGF * KCH_U * 32) {
        int ln = idx & 31, kch = (idx >> 5) % KCH_U, nbg = idx / (32 * KCH_U);
        int n = nbg * 8 + (ln >> 2), tk = ln & 3, kb = kch * 16;
        uint4 v; uint32_t* vp = (uint32_t*)&v;
        #pragma unroll
        for (int q = 0; q < 4; ++q) {
            int k = kb + q * 4 + tk;
            float f = (k < HID && n < 300) ? U_f[k * 300 + n] : 0.0f;
            vp[q] = f2tf(f);
        }
        g_Bf_f[idx] = v;
    }
    if (idx < NC) g_bias[idx] = (idx < 900) ? b_iou[idx] : b_f[idx - 900];
}

// ---------------------------------------------------------------------------
// Shared MMA compute macro pieces (tf32 m16n8k8, warp tile 32x64).
// ---------------------------------------------------------------------------
#define MMA_STEP(ACC, AQ, B0, B1)                                              \
    asm("mma.sync.aligned.m16n8k8.row.col.f32.tf32.tf32.f32 "                  \
        "{%0,%1,%2,%3},{%4,%5,%6,%7},{%8,%9},{%0,%1,%2,%3};"                   \
        : "+f"((ACC)[0]), "+f"((ACC)[1]), "+f"((ACC)[2]), "+f"((ACC)[3])       \
        : "r"((AQ)[0]), "r"((AQ)[1]), "r"((AQ)[2]), "r"((AQ)[3]),              \
          "r"(B0), "r"(B1))

// ---------------------------------------------------------------------------
// gemm_wx: wx = [emb@W_iou+b | emb@W_f+b], M=16320, K=200(pad208), N=1200.
// 3-stage cp.async, single __syncthreads per k-iter. Block 128x128, 256 thr.
// A rows gathered via token-id pointer table (clamped cp.async at row tail).
// ---------------------------------------------------------------------------
__global__ __launch_bounds__(256, 2) void gemm_wx(
    const float* __restrict__ embedTab, const int* __restrict__ xg)
{
    extern __shared__ char smem[];
    float (*As)[128][20] = (float (*)[128][20])smem;                  // 30720 B
    uint4 (*Bs)[16][32]  = (uint4 (*)[16][32])(smem + 3 * 128 * 80);  // 24576 B
    const float** arows  = (const float**)(smem + 3 * 128 * 80 + 3 * 16 * 32 * 16);

    const int tid = threadIdx.x;
    const int rowBase = blockIdx.x * 128;
    const int colBase = blockIdx.y * 128;

    if (tid < 128) {
        int m = rowBase + tid;
        int mc = (m < NROWS) ? m : (NROWS - 1);
        arows[tid] = embedTab + (size_t)xg[mc] * EMB;
    }
    __syncthreads();

    const int lane = tid & 31, warp = tid >> 5;
    const int wm = (warp & 3) * 32, wn = (warp >> 2) * 64;
    const int nbW = wn >> 3;
    const int tg = lane >> 2, tk = lane & 3;
    const int nbgBase = colBase >> 3;

    float acc[2][8][4] = {};

#define FILL_WX(ST, KC)                                                         \
    do {                                                                        \
        int _k0 = (KC) * 16;                                                    \
        _Pragma("unroll")                                                       \
        for (int _i = 0; _i < 2; ++_i) {                                        \
            int _e = tid + _i * 256, _r = _e >> 2, _c = _e & 3;                 \
            uint32_t _d = (uint32_t)__cvta_generic_to_shared(&As[ST][_r][_c*4]);\
            const float* _s = arows[_r] + _k0 + _c * 4;                         \
            int _vb = EMB - (_k0 + _c * 4);                                     \
            int _sz = (_vb >= 4) ? 16 : ((_vb > 0) ? _vb * 4 : 0);              \
            CPA16Z(_d, _s, _sz);                                                \
        }                                                                       \
        _Pragma("unroll")                                                       \
        for (int _i = 0; _i < 2; ++_i) {                                        \
            int _e = tid + _i * 256, _nb = _e >> 5, _ln = _e & 31;              \
            uint32_t _d = (uint32_t)__cvta_generic_to_shared(&Bs[ST][_nb][_ln]);\
            CPA16(_d, g_Bw_f + ((size_t)(nbgBase + _nb) * KCH_E + (KC)) * 32 + _ln); \
        }                                                                       \
        CPCOMMIT();                                                             \
    } while (0)

    FILL_WX(0, 0);
    FILL_WX(1, 1);

    for (int kch = 0; kch < KCH_E; ++kch) {
        const int s = kch % 3;
        if (kch + 1 < KCH_E) { CPWAIT(1); } else { CPWAIT(0); }
        __syncthreads();
        if (kch + 2 < KCH_E) FILL_WX((kch + 2) % 3, kch + 2);

        uint32_t a[2][2][4];
        #pragma unroll
        for (int kb = 0; kb < 2; ++kb)
            #pragma unroll
            for (int mf = 0; mf < 2; ++mf) {
                int r = wm + mf * 16 + tg;
                a[kb][mf][0] = __float_as_uint(As[s][r    ][kb * 8 + tk]);
                a[kb][mf][1] = __float_as_uint(As[s][r + 8][kb * 8 + tk]);
                a[kb][mf][2] = __float_as_uint(As[s][r    ][kb * 8 + tk + 4]);
                a[kb][mf][3] = __float_as_uint(As[s][r + 8][kb * 8 + tk + 4]);
            }
        #pragma unroll
        for (int nf = 0; nf < 8; ++nf) {
            uint4 bq = Bs[s][nbW + nf][lane];
            #pragma unroll
            for (int mf = 0; mf < 2; ++mf) {
                MMA_STEP(acc[mf][nf], a[0][mf], bq.x, bq.y);
                MMA_STEP(acc[mf][nf], a[1][mf], bq.z, bq.w);
            }
        }
    }
#undef FILL_WX

    #pragma unroll
    for (int mf = 0; mf < 2; ++mf)
        #pragma unroll
        for (int nf = 0; nf < 8; ++nf) {
            int row = rowBase + wm + mf * 16 + tg;
            int col = colBase + wn + nf * 8 + tk * 2;
            if (col < NC) {
                float b0 = g_bias[col], b1 = g_bias[col + 1];
                if (row < NROWS)
                    *(float2*)(g_wx + (size_t)row * NC + col) =
                        make_float2(acc[mf][nf][0] + b0, acc[mf][nf][1] + b1);
                if (row + 8 < NROWS)
                    *(float2*)(g_wx + (size_t)(row + 8) * NC + col) =
                        make_float2(acc[mf][nf][2] + b0, acc[mf][nf][3] + b1);
            }
        }
}

// ---------------------------------------------------------------------------
// hsum: g_Hs[i*64+b] = H[(2(p0+i)+1)*64+b] + H[(2(p0+i)+2)*64+b], vectorized.
// ---------------------------------------------------------------------------
__global__ void hsum_kernel(int p0, int np)
{
    int idx = blockIdx.x * blockDim.x + threadIdx.x;
    int tot = np * B_ * 75;                 // 75 float4 = 300 cols
    if (idx >= tot) return;
    int q = idx % 75;
    int r = idx / 75;                       // i*64 + b
    int i = r >> 6, b = r & 63;
    int lc = 2 * (p0 + i) + 1;
    const float4* L = (const float4*)(g_H + (size_t)(lc * B_ + b) * H_LD) + q;
    const float4* R = (const float4*)(g_H + (size_t)((lc + 1) * B_ + b) * H_LD) + q;
    float4 l = *L, rr = *R;
    ((float4*)(g_Hs + (size_t)r * H_LD))[q] =
        make_float4(l.x + rr.x, l.y + rr.y, l.z + rr.z, l.w + rr.w);
}

// ---------------------------------------------------------------------------
// level_gemm: fused per-level GEMMs (affine A, no pointer table).
//  blockIdx.y < 8 : IOU: A = g_Hs (M=np*64),   B=U_iou, N=900  -> g_Ti
//  blockIdx.y >= 8: F:   A = H children (M=nc*64), B=U_f, N=300 -> g_Tf
// A rows have zero-padded cols 300..303 (stride 304) -> no clamping needed.
// ---------------------------------------------------------------------------
__global__ __launch_bounds__(256, 2) void level_gemm(int p0, int np)
{
    extern __shared__ char smem[];
    float (*As)[128][20] = (float (*)[128][20])smem;
    uint4 (*Bs)[16][32]  = (uint4 (*)[16][32])(smem + 3 * 128 * 80);

    const int tid = threadIdx.x;
    const bool isF = (blockIdx.y >= 8);
    const int Mrows = isF ? np * 128 : np * 64;
    const int rowBase = blockIdx.x * 128;
    if (rowBase >= Mrows) return;
    const int colBase = (isF ? (blockIdx.y - 8) : blockIdx.y) * 128;
    const int Nout = isF ? 300 : 900;
    const uint4* gB = isF ? g_Bf_f : g_Bi_f;
    float* Cout = isF ? g_Tf : g_Ti;

    const int lane = tid & 31, warp = tid >> 5;
    const int wm = (warp & 3) * 32, wn = (warp >> 2) * 64;
    const int nbW = wn >> 3;
    const int tg = lane >> 2, tk = lane & 3;
    const int nbgBase = colBase >> 3;

    // affine A source for this thread's cp.async row
    const int ar = tid >> 1;               // 0..127
    const int ac = (tid & 1) << 1;         // {0,2}
    int arow = rowBase + ar; if (arow >= Mrows) arow = Mrows - 1;
    const float* asrc = isF
        ? g_H  + (size_t)((2 * p0 + 1) * B_ + arow) * H_LD
        : g_Hs + (size_t)arow * H_LD;

    float acc[2][8][4] = {};

#define FILL_LV(ST, KC)                                                         \
    do {                                                                        \
        int _k0 = (KC) * 16;                                                    \
        _Pragma("unroll")                                                       \
        for (int _i = 0; _i < 2; ++_i) {                                        \
            int _c = ac + _i;                                                   \
            uint32_t _d = (uint32_t)__cvta_generic_to_shared(&As[ST][ar][_c*4]);\
            CPA16(_d, asrc + _k0 + _c * 4);                                     \
        }                                                                       \
        _Pragma("unroll")                                                       \
        for (int _i = 0; _i < 2; ++_i) {                                        \
            int _e = tid + _i * 256, _nb = _e >> 5, _ln = _e & 31;              \
            uint32_t _d = (uint32_t)__cvta_generic_to_shared(&Bs[ST][_nb][_ln]);\
            CPA16(_d, gB + ((size_t)(nbgBase + _nb) * KCH_U + (KC)) * 32 + _ln);\
        }                                                                       \
        CPCOMMIT();                                                             \
    } while (0)

    FILL_LV(0, 0);
    FILL_LV(1, 1);

    for (int kch = 0; kch < KCH_U; ++kch) {
        const int s = kch % 3;
        if (kch + 1 < KCH_U) { CPWAIT(1); } else { CPWAIT(0); }
        __syncthreads();
        if (kch + 2 < KCH_U) FILL_LV((kch + 2) % 3, kch + 2);

        uint32_t a[2][2][4];
        #pragma unroll
        for (int kb = 0; kb < 2; ++kb)
            #pragma unroll
            for (int mf = 0; mf < 2; ++mf) {
                int r = wm + mf * 16 + tg;
                a[kb][mf][0] = __float_as_uint(As[s][r    ][kb * 8 + tk]);
                a[kb][mf][1] = __float_as_uint(As[s][r + 8][kb * 8 + tk]);
                a[kb][mf][2] = __float_as_uint(As[s][r    ][kb * 8 + tk + 4]);
                a[kb][mf][3] = __float_as_uint(As[s][r + 8][kb * 8 + tk + 4]);
            }
        #pragma unroll
        for (int nf = 0; nf < 8; ++nf) {
            uint4 bq = Bs[s][nbW + nf][lane];
            #pragma unroll
            for (int mf = 0; mf < 2; ++mf) {
                MMA_STEP(acc[mf][nf], a[0][mf], bq.x, bq.y);
                MMA_STEP(acc[mf][nf], a[1][mf], bq.z, bq.w);
            }
        }
    }
#undef FILL_LV

    #pragma unroll
    for (int mf = 0; mf < 2; ++mf)
        #pragma unroll
        for (int nf = 0; nf < 8; ++nf) {
            int row = rowBase + wm + mf * 16 + tg;
            int col = colBase + wn + nf * 8 + tk * 2;
            if (col < Nout) {
                if (row < Mrows)
                    *(float2*)(Cout + (size_t)row * Nout + col) =
                        make_float2(acc[mf][nf][0], acc[mf][nf][1]);
                if (row + 8 < Mrows)
                    *(float2*)(Cout + (size_t)(row + 8) * Nout + col) =
                        make_float2(acc[mf][nf][2], acc[mf][nf][3]);
            }
        }
}

// ---------------------------------------------------------------------------
// Leaves (nodes 127..254)
// ---------------------------------------------------------------------------
__global__ void leaf_kernel()
{
    int idx = blockIdx.x * blockDim.x + threadIdx.x;
    if (idx >= 128 * B_ * HID) return;
    int n = idx % HID;
    int r = idx / HID;
    int row = 127 * B_ + r;
    const float* wx = g_wx + (size_t)row * NC;
    float iv = sigmoidf(wx[n]);
    float ov = sigmoidf(wx[300 + n]);
    float uv = tanhf(wx[600 + n]);
    float c = iv * uv;
    g_C[(size_t)row * HID + n] = c;
    g_H[(size_t)row * H_LD + n] = ov * tanhf(c);
}

// ---------------------------------------------------------------------------
// Per-level combine: parents p0..p0+np-1 (Ti ldc=900, Tf ldc=300).
// ---------------------------------------------------------------------------
__global__ void level_pw(int p0, int np)
{
    int idx = blockIdx.x * blockDim.x + threadIdx.x;
    int tot = np * B_ * HID;
    if (idx >= tot) return;
    int n  = idx % HID;
    int r  = idx / HID;      // pi*64 + b
    int b  = r % B_;
    int pi = r / B_;
    int p  = p0 + pi;

    const float* wx = g_wx + (size_t)(p * B_ + b) * NC;
    const float* ti = g_Ti + (size_t)r * 900;

    float iv = sigmoidf(wx[n]       + ti[n]);
    float ov = sigmoidf(wx[300 + n] + ti[300 + n]);
    float uv = tanhf   (wx[600 + n] + ti[600 + n]);
    float wf = wx[900 + n];
    float fl = sigmoidf(wf + g_Tf[(size_t)((2 * pi    ) * B_ + b) * 300 + n]);
    float fr = sigmoidf(wf + g_Tf[(size_t)((2 * pi + 1) * B_ + b) * 300 + n]);

    int lc = 2 * p + 1, rc = 2 * p + 2;
    float fc = fl * g_C[(size_t)(lc * B_ + b) * HID + n]
             + fr * g_C[(size_t)(rc * B_ + b) * HID + n];
    float c = iv * uv + fc;
    float h = ov * tanhf(c);
    g_C[(size_t)(p * B_ + b) * HID + n] = c;
    g_H[(size_t)(p * B_ + b) * H_LD + n] = h;
}

// ---------------------------------------------------------------------------
// Output head
// ---------------------------------------------------------------------------
__global__ __launch_bounds__(64) void out_kernel(
    const float* __restrict__ W_out, const float* __restrict__ b_out,
    float* __restrict__ out)
{
    const int b = threadIdx.x;
    const float* h = g_H + (size_t)b * H_LD;   // node 0 rows
    float l0 = b_out[0], l1 = b_out[1];
    #pragma unroll 4
    for (int k = 0; k < HID; ++k) {
        float hv = h[k];
        l0 = fmaf(hv, W_out[k * 2 + 0], l0);
        l1 = fmaf(hv, W_out[k * 2 + 1], l1);
    }
    float m   = fmaxf(l0, l1);
    float lse = m + logf(expf(l0 - m) + expf(l1 - m));
    out[b * 2 + 0] = l0 - lse;
    out[b * 2 + 1] = l1 - lse;
}

// ---------------------------------------------------------------------------
extern "C" void kernel_launch(void* const* d_in, const int* in_sizes, int n_in,
                              void* d_out, int out_size)
{
    (void)in_sizes; (void)n_in; (void)out_size;
    const int*   x     = (const int*)  d_in[0];
    const float* embed = (const float*)d_in[3];
    const float* W_iou = (const float*)d_in[4];
    const float* U_iou = (const float*)d_in[5];
    const float* b_iou = (const float*)d_in[6];
    const float* W_f   = (const float*)d_in[7];
    const float* U_f   = (const float*)d_in[8];
    const float* b_f   = (const float*)d_in[9];
    const float* W_out = (const float*)d_in[10];
    const float* b_out = (const float*)d_in[11];

    const int SMEM_WX = 3 * 128 * 80 + 3 * 16 * 32 * 16 + 128 * 8;  // 56344
    const int SMEM_LV = 3 * 128 * 80 + 3 * 16 * 32 * 16;            // 55296
    cudaFuncSetAttribute(gemm_wx,    cudaFuncAttributeMaxDynamicSharedMemorySize, SMEM_WX);
    cudaFuncSetAttribute(level_gemm, cudaFuncAttributeMaxDynamicSharedMemorySize, SMEM_LV);

    prep_kernel<<<(NBGI * KCH_U * 32 + 255) / 256, 256>>>(W_iou, W_f, U_iou, U_f, b_iou, b_f);

    gemm_wx<<<dim3(128, 10), 256, SMEM_WX>>>(embed, x);
    leaf_kernel<<<(128 * B_ * HID + 255) / 256, 256>>>();

    for (int d = 6; d >= 0; --d) {
        int np = 1 << d;
        int p0 = np - 1;
        hsum_kernel<<<(np * B_ * 75 + 255) / 256, 256>>>(p0, np);
        level_gemm<<<dim3(np, 11), 256, SMEM_LV>>>(p0, np);
        level_pw<<<(np * B_ * HID + 255) / 256, 256>>>(p0, np);
    }

    out_kernel<<<1, 64>>>(W_out, b_out, (float*)d_out);
}

// round 9
// speedup vs baseline: 1.1305x; 1.0319x over previous
#include <cuda_runtime.h>
#include <math.h>
#include <stdint.h>

#define SN    255
#define B_    64
#define EMB   200
#define HID   300
#define NROWS (SN * B_)     // 16320
#define NC    1200
#define H_LD  304           // padded fp32 row stride for H / Hsum
#define KCH_E 13            // ceil(200/16)
#define KCH_U 19            // ceil(300/16)
#define NBG0  160           // wx B groups  (1280 padded cols)
#define NBGI  128           // U_iou groups (1024 padded cols, N=900)
#define NBGF  48            // U_f groups   (384 padded cols,  N=300)

// ---- device scratch (device globals zero-initialized at load; padding cols stay 0) ----
__device__ float g_wx[NROWS * NC];
__device__ float g_H [NROWS * H_LD + 64];
__device__ float g_Hs[64 * B_ * H_LD + 64];   // h_sum rows for current level's iou GEMM
__device__ float g_C [NROWS * HID];
__device__ float g_Ti[64 * B_ * 900];         // iou GEMM out (parents)
__device__ float g_Tf[128 * B_ * 300];        // f GEMM out (children)
__device__ uint4 g_Bw_f[NBG0 * KCH_E * 32];
__device__ uint4 g_Bi_f[NBGI * KCH_U * 32];
__device__ uint4 g_Bf_f[NBGF * KCH_U * 32];
__device__ float g_bias[NC];

__device__ __forceinline__ float sigmoidf(float x) { return 1.0f / (1.0f + expf(-x)); }
__device__ __forceinline__ uint32_t f2tf(float x) {
    uint32_t u; asm("cvt.rna.tf32.f32 %0, %1;" : "=r"(u) : "f"(x)); return u;
}

// ---- cp.async helpers ----
#define CPA16(dst, src) \
    asm volatile("cp.async.ca.shared.global [%0], [%1], 16;" :: "r"(dst), "l"(src))
#define CPA16Z(dst, src, sz) \
    asm volatile("cp.async.ca.shared.global [%0], [%1], 16, %2;" :: "r"(dst), "l"(src), "r"(sz))
#define CPCOMMIT() asm volatile("cp.async.commit_group;")
#define CPWAIT(n)  asm volatile("cp.async.wait_group %0;" :: "n"(n))

// ---------------------------------------------------------------------------
// Prep: pack the three B matrices into tf32 fragment order + concat bias.
// ---------------------------------------------------------------------------
__global__ void prep_kernel(const float* __restrict__ W_iou, const float* __restrict__ W_f,
                            const float* __restrict__ U_iou, const float* __restrict__ U_f,
                            const float* __restrict__ b_iou, const float* __restrict__ b_f)
{
    int idx = blockIdx.x * blockDim.x + threadIdx.x;

    if (idx < NBG0 * KCH_E * 32) {
        int ln = idx & 31, kch = (idx >> 5) % KCH_E, nbg = idx / (32 * KCH_E);
        int n = nbg * 8 + (ln >> 2), tk = ln & 3, kb = kch * 16;
        uint4 v; uint32_t* vp = (uint32_t*)&v;
        #pragma unroll
        for (int q = 0; q < 4; ++q) {
            int k = kb + q * 4 + tk;
            float f = 0.0f;
            if (k < EMB && n < NC)
                f = (n < 900) ? W_iou[k * 900 + n] : W_f[k * 300 + (n - 900)];
            vp[q] = f2tf(f);
        }
        g_Bw_f[idx] = v;
    }
    if (idx < NBGI * KCH_U * 32) {
        int ln = idx & 31, kch = (idx >> 5) % KCH_U, nbg = idx / (32 * KCH_U);
        int n = nbg * 8 + (ln >> 2), tk = ln & 3, kb = kch * 16;
        uint4 v; uint32_t* vp = (uint32_t*)&v;
        #pragma unroll
        for (int q = 0; q < 4; ++q) {
            int k = kb + q * 4 + tk;
            float f = (k < HID && n < 900) ? U_iou[k * 900 + n] : 0.0f;
            vp[q] = f2tf(f);
        }
        g_Bi_f[idx] = v;
    }
    if (idx < NBGF * KCH_U * 32) {
        int ln = idx & 31, kch = (idx >> 5) % KCH_U, nbg = idx / (32 * KCH_U);
        int n = nbg * 8 + (ln >> 2), tk = ln & 3, kb = kch * 16;
        uint4 v; uint32_t* vp = (uint32_t*)&v;
        #pragma unroll
        for (int q = 0; q < 4; ++q) {
            int k = kb + q * 4 + tk;
            float f = (k < HID && n < 300) ? U_f[k * 300 + n] : 0.0f;
            vp[q] = f2tf(f);
        }
        g_Bf_f[idx] = v;
    }
    if (idx < NC) g_bias[idx] = (idx < 900) ? b_iou[idx] : b_f[idx - 900];
}

#define MMA_STEP(ACC, AQ, B0, B1)                                              \
    asm("mma.sync.aligned.m16n8k8.row.col.f32.tf32.tf32.f32 "                  \
        "{%0,%1,%2,%3},{%4,%5,%6,%7},{%8,%9},{%0,%1,%2,%3};"                   \
        : "+f"((ACC)[0]), "+f"((ACC)[1]), "+f"((ACC)[2]), "+f"((ACC)[3])       \
        : "r"((AQ)[0]), "r"((AQ)[1]), "r"((AQ)[2]), "r"((AQ)[3]),              \
          "r"(B0), "r"(B1))

// ---------------------------------------------------------------------------
// gemm_wx: wx = [emb@W_iou+b | emb@W_f+b], M=16320, K=200, N=1200.
// ---------------------------------------------------------------------------
__global__ __launch_bounds__(256, 2) void gemm_wx(
    const float* __restrict__ embedTab, const int* __restrict__ xg)
{
    extern __shared__ char smem[];
    float (*As)[128][20] = (float (*)[128][20])smem;
    uint4 (*Bs)[16][32]  = (uint4 (*)[16][32])(smem + 3 * 128 * 80);
    const float** arows  = (const float**)(smem + 3 * 128 * 80 + 3 * 16 * 32 * 16);

    const int tid = threadIdx.x;
    const int rowBase = blockIdx.x * 128;
    const int colBase = blockIdx.y * 128;

    if (tid < 128) {
        int m = rowBase + tid;
        int mc = (m < NROWS) ? m : (NROWS - 1);
        arows[tid] = embedTab + (size_t)xg[mc] * EMB;
    }
    __syncthreads();

    const int lane = tid & 31, warp = tid >> 5;
    const int wm = (warp & 3) * 32, wn = (warp >> 2) * 64;
    const int nbW = wn >> 3;
    const int tg = lane >> 2, tk = lane & 3;
    const int nbgBase = colBase >> 3;

    float acc[2][8][4] = {};

#define FILL_WX(ST, KC)                                                         \
    do {                                                                        \
        int _k0 = (KC) * 16;                                                    \
        _Pragma("unroll")                                                       \
        for (int _i = 0; _i < 2; ++_i) {                                        \
            int _e = tid + _i * 256, _r = _e >> 2, _c = _e & 3;                 \
            uint32_t _d = (uint32_t)__cvta_generic_to_shared(&As[ST][_r][_c*4]);\
            const float* _s = arows[_r] + _k0 + _c * 4;                         \
            int _vb = EMB - (_k0 + _c * 4);                                     \
            int _sz = (_vb >= 4) ? 16 : ((_vb > 0) ? _vb * 4 : 0);              \
            CPA16Z(_d, _s, _sz);                                                \
        }                                                                       \
        _Pragma("unroll")                                                       \
        for (int _i = 0; _i < 2; ++_i) {                                        \
            int _e = tid + _i * 256, _nb = _e >> 5, _ln = _e & 31;              \
            uint32_t _d = (uint32_t)__cvta_generic_to_shared(&Bs[ST][_nb][_ln]);\
            CPA16(_d, g_Bw_f + ((size_t)(nbgBase + _nb) * KCH_E + (KC)) * 32 + _ln); \
        }                                                                       \
        CPCOMMIT();                                                             \
    } while (0)

    FILL_WX(0, 0);
    FILL_WX(1, 1);

    for (int kch = 0; kch < KCH_E; ++kch) {
        const int s = kch % 3;
        if (kch + 1 < KCH_E) { CPWAIT(1); } else { CPWAIT(0); }
        __syncthreads();
        if (kch + 2 < KCH_E) FILL_WX((kch + 2) % 3, kch + 2);

        uint32_t a[2][2][4];
        #pragma unroll
        for (int kb = 0; kb < 2; ++kb)
            #pragma unroll
            for (int mf = 0; mf < 2; ++mf) {
                int r = wm + mf * 16 + tg;
                a[kb][mf][0] = __float_as_uint(As[s][r    ][kb * 8 + tk]);
                a[kb][mf][1] = __float_as_uint(As[s][r + 8][kb * 8 + tk]);
                a[kb][mf][2] = __float_as_uint(As[s][r    ][kb * 8 + tk + 4]);
                a[kb][mf][3] = __float_as_uint(As[s][r + 8][kb * 8 + tk + 4]);
            }
        #pragma unroll
        for (int nf = 0; nf < 8; ++nf) {
            uint4 bq = Bs[s][nbW + nf][lane];
            #pragma unroll
            for (int mf = 0; mf < 2; ++mf) {
                MMA_STEP(acc[mf][nf], a[0][mf], bq.x, bq.y);
                MMA_STEP(acc[mf][nf], a[1][mf], bq.z, bq.w);
            }
        }
    }
#undef FILL_WX

    #pragma unroll
    for (int mf = 0; mf < 2; ++mf)
        #pragma unroll
        for (int nf = 0; nf < 8; ++nf) {
            int row = rowBase + wm + mf * 16 + tg;
            int col = colBase + wn + nf * 8 + tk * 2;
            if (col < NC) {
                float b0 = g_bias[col], b1 = g_bias[col + 1];
                if (row < NROWS)
                    *(float2*)(g_wx + (size_t)row * NC + col) =
                        make_float2(acc[mf][nf][0] + b0, acc[mf][nf][1] + b1);
                if (row + 8 < NROWS)
                    *(float2*)(g_wx + (size_t)(row + 8) * NC + col) =
                        make_float2(acc[mf][nf][2] + b0, acc[mf][nf][3] + b1);
            }
        }
}

// ---------------------------------------------------------------------------
// level_gemm: fused per-level GEMMs (affine A).
//  blockIdx.y < 8 : IOU: A = g_Hs (M=np*64), B=U_iou, N=900 -> g_Ti
//  blockIdx.y >= 8: F:   A = H children (M=np*128), B=U_f, N=300 -> g_Tf
// ---------------------------------------------------------------------------
__global__ __launch_bounds__(256, 2) void level_gemm(int p0, int np)
{
    extern __shared__ char smem[];
    float (*As)[128][20] = (float (*)[128][20])smem;
    uint4 (*Bs)[16][32]  = (uint4 (*)[16][32])(smem + 3 * 128 * 80);

    const int tid = threadIdx.x;
    const bool isF = (blockIdx.y >= 8);
    const int Mrows = isF ? np * 128 : np * 64;
    const int rowBase = blockIdx.x * 128;
    if (rowBase >= Mrows) return;
    const int colBase = (isF ? (blockIdx.y - 8) : blockIdx.y) * 128;
    const int Nout = isF ? 300 : 900;
    const uint4* gB = isF ? g_Bf_f : g_Bi_f;
    float* Cout = isF ? g_Tf : g_Ti;

    const int lane = tid & 31, warp = tid >> 5;
    const int wm = (warp & 3) * 32, wn = (warp >> 2) * 64;
    const int nbW = wn >> 3;
    const int tg = lane >> 2, tk = lane & 3;
    const int nbgBase = colBase >> 3;

    const int ar = tid >> 1;
    const int ac = (tid & 1) << 1;
    int arow = rowBase + ar; if (arow >= Mrows) arow = Mrows - 1;
    const float* asrc = isF
        ? g_H  + (size_t)((2 * p0 + 1) * B_ + arow) * H_LD
        : g_Hs + (size_t)arow * H_LD;

    float acc[2][8][4] = {};

#define FILL_LV(ST, KC)                                                         \
    do {                                                                        \
        int _k0 = (KC) * 16;                                                    \
        _Pragma("unroll")                                                       \
        for (int _i = 0; _i < 2; ++_i) {                                        \
            int _c = ac + _i;                                                   \
            uint32_t _d = (uint32_t)__cvta_generic_to_shared(&As[ST][ar][_c*4]);\
            CPA16(_d, asrc + _k0 + _c * 4);                                     \
        }                                                                       \
        _Pragma("unroll")                                                       \
        for (int _i = 0; _i < 2; ++_i) {                                        \
            int _e = tid + _i * 256, _nb = _e >> 5, _ln = _e & 31;              \
            uint32_t _d = (uint32_t)__cvta_generic_to_shared(&Bs[ST][_nb][_ln]);\
            CPA16(_d, gB + ((size_t)(nbgBase + _nb) * KCH_U + (KC)) * 32 + _ln);\
        }                                                                       \
        CPCOMMIT();                                                             \
    } while (0)

    FILL_LV(0, 0);
    FILL_LV(1, 1);

    for (int kch = 0; kch < KCH_U; ++kch) {
        const int s = kch % 3;
        if (kch + 1 < KCH_U) { CPWAIT(1); } else { CPWAIT(0); }
        __syncthreads();
        if (kch + 2 < KCH_U) FILL_LV((kch + 2) % 3, kch + 2);

        uint32_t a[2][2][4];
        #pragma unroll
        for (int kb = 0; kb < 2; ++kb)
            #pragma unroll
            for (int mf = 0; mf < 2; ++mf) {
                int r = wm + mf * 16 + tg;
                a[kb][mf][0] = __float_as_uint(As[s][r    ][kb * 8 + tk]);
                a[kb][mf][1] = __float_as_uint(As[s][r + 8][kb * 8 + tk]);
                a[kb][mf][2] = __float_as_uint(As[s][r    ][kb * 8 + tk + 4]);
                a[kb][mf][3] = __float_as_uint(As[s][r + 8][kb * 8 + tk + 4]);
            }
        #pragma unroll
        for (int nf = 0; nf < 8; ++nf) {
            uint4 bq = Bs[s][nbW + nf][lane];
            #pragma unroll
            for (int mf = 0; mf < 2; ++mf) {
                MMA_STEP(acc[mf][nf], a[0][mf], bq.x, bq.y);
                MMA_STEP(acc[mf][nf], a[1][mf], bq.z, bq.w);
            }
        }
    }
#undef FILL_LV

    #pragma unroll
    for (int mf = 0; mf < 2; ++mf)
        #pragma unroll
        for (int nf = 0; nf < 8; ++nf) {
            int row = rowBase + wm + mf * 16 + tg;
            int col = colBase + wn + nf * 8 + tk * 2;
            if (col < Nout) {
                if (row < Mrows)
                    *(float2*)(Cout + (size_t)row * Nout + col) =
                        make_float2(acc[mf][nf][0], acc[mf][nf][1]);
                if (row + 8 < Mrows)
                    *(float2*)(Cout + (size_t)(row + 8) * Nout + col) =
                        make_float2(acc[mf][nf][2], acc[mf][nf][3]);
            }
        }
}

// ---------------------------------------------------------------------------
// Leaves, sibling-paired: pair j = nodes (127+2j, 128+2j), parent 63+j.
// Writes H, C for both leaves and Hs row j*64+b for the d=6 iou GEMM.
// ---------------------------------------------------------------------------
__global__ void leaf_kernel()
{
    int idx = blockIdx.x * blockDim.x + threadIdx.x;
    if (idx >= 64 * B_ * HID) return;
    int n = idx % HID;
    int r = idx / HID;       // j*64 + b
    int b = r % B_;
    int j = r / B_;

    float hs = 0.0f;
    #pragma unroll
    for (int s = 0; s < 2; ++s) {
        int node = 127 + 2 * j + s;
        int row  = node * B_ + b;
        const float* wx = g_wx + (size_t)row * NC;
        float iv = sigmoidf(wx[n]);
        float ov = sigmoidf(wx[300 + n]);
        float uv = tanhf(wx[600 + n]);
        float c  = iv * uv;
        float h  = ov * tanhf(c);
        g_C[(size_t)row * HID + n] = c;
        g_H[(size_t)row * H_LD + n] = h;
        hs += h;
    }
    g_Hs[(size_t)r * H_LD + n] = hs;
}

// ---------------------------------------------------------------------------
// level_pw_pair (d >= 1, np even): thread handles BOTH sibling parents
// (p0+2i, p0+2i+1); writes H, C for both and Hs row i*64+b for level d-1.
// ---------------------------------------------------------------------------
__device__ __forceinline__ float node_gate(int p0, int pi, int b, int n, float* cOut)
{
    int p = p0 + pi;
    const float* wx = g_wx + (size_t)(p * B_ + b) * NC;
    const float* ti = g_Ti + (size_t)(pi * B_ + b) * 900;
    float iv = sigmoidf(wx[n]       + ti[n]);
    float ov = sigmoidf(wx[300 + n] + ti[300 + n]);
    float uv = tanhf   (wx[600 + n] + ti[600 + n]);
    float wf = wx[900 + n];
    float fl = sigmoidf(wf + g_Tf[(size_t)((2 * pi    ) * B_ + b) * 300 + n]);
    float fr = sigmoidf(wf + g_Tf[(size_t)((2 * pi + 1) * B_ + b) * 300 + n]);
    int lc = 2 * p + 1, rc = 2 * p + 2;
    float fc = fl * g_C[(size_t)(lc * B_ + b) * HID + n]
             + fr * g_C[(size_t)(rc * B_ + b) * HID + n];
    float c = iv * uv + fc;
    *cOut = c;
    return ov * tanhf(c);
}

__global__ void level_pw_pair(int p0, int np)
{
    int idx = blockIdx.x * blockDim.x + threadIdx.x;
    int tot = (np >> 1) * B_ * HID;
    if (idx >= tot) return;
    int n = idx % HID;
    int r = idx / HID;       // i*64 + b
    int b = r % B_;
    int i = r / B_;

    float cL, cR;
    float hL = node_gate(p0, 2 * i,     b, n, &cL);
    float hR = node_gate(p0, 2 * i + 1, b, n, &cR);

    int pL = p0 + 2 * i, pR = pL + 1;
    g_C[(size_t)(pL * B_ + b) * HID + n] = cL;
    g_C[(size_t)(pR * B_ + b) * HID + n] = cR;
    g_H[(size_t)(pL * B_ + b) * H_LD + n] = hL;
    g_H[(size_t)(pR * B_ + b) * H_LD + n] = hR;
    g_Hs[(size_t)r * H_LD + n] = hL + hR;
}

// Root (d=0): single node, no Hs.
__global__ void level_pw_root()
{
    int idx = blockIdx.x * blockDim.x + threadIdx.x;
    if (idx >= B_ * HID) return;
    int n = idx % HID;
    int b = idx / HID;
    float c;
    float h = node_gate(0, 0, b, n, &c);
    g_C[(size_t)b * HID + n] = c;
    g_H[(size_t)b * H_LD + n] = h;
}

// ---------------------------------------------------------------------------
// Output head
// ---------------------------------------------------------------------------
__global__ __launch_bounds__(64) void out_kernel(
    const float* __restrict__ W_out, const float* __restrict__ b_out,
    float* __restrict__ out)
{
    const int b = threadIdx.x;
    const float* h = g_H + (size_t)b * H_LD;
    float l0 = b_out[0], l1 = b_out[1];
    #pragma unroll 4
    for (int k = 0; k < HID; ++k) {
        float hv = h[k];
        l0 = fmaf(hv, W_out[k * 2 + 0], l0);
        l1 = fmaf(hv, W_out[k * 2 + 1], l1);
    }
    float m   = fmaxf(l0, l1);
    float lse = m + logf(expf(l0 - m) + expf(l1 - m));
    out[b * 2 + 0] = l0 - lse;
    out[b * 2 + 1] = l1 - lse;
}

// ---------------------------------------------------------------------------
extern "C" void kernel_launch(void* const* d_in, const int* in_sizes, int n_in,
                              void* d_out, int out_size)
{
    (void)in_sizes; (void)n_in; (void)out_size;
    const int*   x     = (const int*)  d_in[0];
    const float* embed = (const float*)d_in[3];
    const float* W_iou = (const float*)d_in[4];
    const float* U_iou = (const float*)d_in[5];
    const float* b_iou = (const float*)d_in[6];
    const float* W_f   = (const float*)d_in[7];
    const float* U_f   = (const float*)d_in[8];
    const float* b_f   = (const float*)d_in[9];
    const float* W_out = (const float*)d_in[10];
    const float* b_out = (const float*)d_in[11];

    const int SMEM_WX = 3 * 128 * 80 + 3 * 16 * 32 * 16 + 128 * 8;
    const int SMEM_LV = 3 * 128 * 80 + 3 * 16 * 32 * 16;
    cudaFuncSetAttribute(gemm_wx,    cudaFuncAttributeMaxDynamicSharedMemorySize, SMEM_WX);
    cudaFuncSetAttribute(level_gemm, cudaFuncAttributeMaxDynamicSharedMemorySize, SMEM_LV);

    prep_kernel<<<(NBGI * KCH_U * 32 + 255) / 256, 256>>>(W_iou, W_f, U_iou, U_f, b_iou, b_f);

    gemm_wx<<<dim3(128, 10), 256, SMEM_WX>>>(embed, x);
    leaf_kernel<<<(64 * B_ * HID + 255) / 256, 256>>>();   // H, C for leaves + Hs for d=6

    for (int d = 6; d >= 1; --d) {
        int np = 1 << d;
        int p0 = np - 1;
        level_gemm<<<dim3(np, 11), 256, SMEM_LV>>>(p0, np);
        level_pw_pair<<<((np / 2) * B_ * HID + 255) / 256, 256>>>(p0, np);
    }
    // root
    level_gemm<<<dim3(1, 11), 256, SMEM_LV>>>(0, 1);
    level_pw_root<<<(B_ * HID + 255) / 256, 256>>>();

    out_kernel<<<1, 64>>>(W_out, b_out, (float*)d_out);
}

// round 10
// speedup vs baseline: 1.3519x; 1.1959x over previous
#include <cuda_runtime.h>
#include <math.h>
#include <stdint.h>

#define SN    255
#define B_    64
#define EMB   200
#define HID   300
#define NROWS (SN * B_)     // 16320
#define NC    1200
#define H_LD  304           // padded fp32 row stride for H / Hsum
#define KCH_E 13            // ceil(200/16)
#define KCH_U 19            // ceil(300/16)
#define NBG0  160
#define NBGI  128
#define NBGF  48

// ---- device scratch (zero-initialized at load; padding cols stay 0) ----
__device__ float g_wx[NROWS * NC];
__device__ float g_H [NROWS * H_LD + 64];
__device__ float g_Hs[64 * B_ * H_LD + 64];
__device__ float g_C [NROWS * HID];
__device__ float g_Ti[64 * B_ * 900];
__device__ float g_Tf[128 * B_ * 300];
__device__ uint4 g_Bw_f[NBG0 * KCH_E * 32];
__device__ uint4 g_Bi_f[NBGI * KCH_U * 32];
__device__ uint4 g_Bf_f[NBGF * KCH_U * 32];
__device__ float g_bias[NC];

__device__ __forceinline__ float sigmoidf(float x) { return 1.0f / (1.0f + expf(-x)); }
__device__ __forceinline__ uint32_t f2tf(float x) {
    uint32_t u; asm("cvt.rna.tf32.f32 %0, %1;" : "=r"(u) : "f"(x)); return u;
}

#define CPA16(dst, src) \
    asm volatile("cp.async.ca.shared.global [%0], [%1], 16;" :: "r"(dst), "l"(src))
#define CPA16Z(dst, src, sz) \
    asm volatile("cp.async.ca.shared.global [%0], [%1], 16, %2;" :: "r"(dst), "l"(src), "r"(sz))
#define CPCOMMIT() asm volatile("cp.async.commit_group;")
#define CPWAIT(n)  asm volatile("cp.async.wait_group %0;" :: "n"(n))

// ---------------------------------------------------------------------------
// Prep: pack three B matrices into tf32 fragment order + concat bias.
// ---------------------------------------------------------------------------
__global__ void prep_kernel(const float* __restrict__ W_iou, const float* __restrict__ W_f,
                            const float* __restrict__ U_iou, const float* __restrict__ U_f,
                            const float* __restrict__ b_iou, const float* __restrict__ b_f)
{
    int idx = blockIdx.x * blockDim.x + threadIdx.x;

    if (idx < NBG0 * KCH_E * 32) {
        int ln = idx & 31, kch = (idx >> 5) % KCH_E, nbg = idx / (32 * KCH_E);
        int n = nbg * 8 + (ln >> 2), tk = ln & 3, kb = kch * 16;
        uint4 v; uint32_t* vp = (uint32_t*)&v;
        #pragma unroll
        for (int q = 0; q < 4; ++q) {
            int k = kb + q * 4 + tk;
            float f = 0.0f;
            if (k < EMB && n < NC)
                f = (n < 900) ? W_iou[k * 900 + n] : W_f[k * 300 + (n - 900)];
            vp[q] = f2tf(f);
        }
        g_Bw_f[idx] = v;
    }
    if (idx < NBGI * KCH_U * 32) {
        int ln = idx & 31, kch = (idx >> 5) % KCH_U, nbg = idx / (32 * KCH_U);
        int n = nbg * 8 + (ln >> 2), tk = ln & 3, kb = kch * 16;
        uint4 v; uint32_t* vp = (uint32_t*)&v;
        #pragma unroll
        for (int q = 0; q < 4; ++q) {
            int k = kb + q * 4 + tk;
            float f = (k < HID && n < 900) ? U_iou[k * 900 + n] : 0.0f;
            vp[q] = f2tf(f);
        }
        g_Bi_f[idx] = v;
    }
    if (idx < NBGF * KCH_U * 32) {
        int ln = idx & 31, kch = (idx >> 5) % KCH_U, nbg = idx / (32 * KCH_U);
        int n = nbg * 8 + (ln >> 2), tk = ln & 3, kb = kch * 16;
        uint4 v; uint32_t* vp = (uint32_t*)&v;
        #pragma unroll
        for (int q = 0; q < 4; ++q) {
            int k = kb + q * 4 + tk;
            float f = (k < HID && n < 300) ? U_f[k * 300 + n] : 0.0f;
            vp[q] = f2tf(f);
        }
        g_Bf_f[idx] = v;
    }
    if (idx < NC) g_bias[idx] = (idx < 900) ? b_iou[idx] : b_f[idx - 900];
}

#define MMA_STEP(ACC, AQ, B0, B1)                                              \
    asm("mma.sync.aligned.m16n8k8.row.col.f32.tf32.tf32.f32 "                  \
        "{%0,%1,%2,%3},{%4,%5,%6,%7},{%8,%9},{%0,%1,%2,%3};"                   \
        : "+f"((ACC)[0]), "+f"((ACC)[1]), "+f"((ACC)[2]), "+f"((ACC)[3])       \
        : "r"((AQ)[0]), "r"((AQ)[1]), "r"((AQ)[2]), "r"((AQ)[3]),              \
          "r"(B0), "r"(B1))

// ldmatrix.x4 on tf32 data: one instr per (kb,mf) A fragment.
// lane 0-7 -> rows r0+l, col kb*8; 8-15 -> r0+8+l; 16-23 -> r0+l col +4; 24-31 -> r0+8+l col +4.
#define LDSM_A(AQ, ASBASE, R0, KB)                                             \
    do {                                                                       \
        const float* _p = (ASBASE) +                                           \
            ((R0) + (lane & 7) + ((lane >> 3) & 1) * 8) * 20 +                 \
            (KB) * 8 + (lane >> 4) * 4;                                        \
        uint32_t _ad = (uint32_t)__cvta_generic_to_shared(_p);                 \
        asm volatile("ldmatrix.sync.aligned.m8n8.x4.shared.b16 "               \
                     "{%0,%1,%2,%3},[%4];"                                     \
                     : "=r"((AQ)[0]), "=r"((AQ)[1]), "=r"((AQ)[2]), "=r"((AQ)[3]) \
                     : "r"(_ad));                                              \
    } while (0)

// ---------------------------------------------------------------------------
// gemm_wx: wx = [emb@W_iou+b | emb@W_f+b], M=16320, K=200, N=1200.
// ---------------------------------------------------------------------------
__global__ __launch_bounds__(256, 2) void gemm_wx(
    const float* __restrict__ embedTab, const int* __restrict__ xg)
{
    extern __shared__ char smem[];
    float (*As)[128][20] = (float (*)[128][20])smem;
    uint4 (*Bs)[16][32]  = (uint4 (*)[16][32])(smem + 3 * 128 * 80);
    const float** arows  = (const float**)(smem + 3 * 128 * 80 + 3 * 16 * 32 * 16);

    const int tid = threadIdx.x;
    const int rowBase = blockIdx.x * 128;
    const int colBase = blockIdx.y * 128;

    if (tid < 128) {
        int m = rowBase + tid;
        int mc = (m < NROWS) ? m : (NROWS - 1);
        arows[tid] = embedTab + (size_t)xg[mc] * EMB;
    }
    __syncthreads();

    const int lane = tid & 31, warp = tid >> 5;
    const int wm = (warp & 3) * 32, wn = (warp >> 2) * 64;
    const int nbW = wn >> 3;
    const int tg = lane >> 2, tk = lane & 3;
    const int nbgBase = colBase >> 3;

    float acc[2][8][4] = {};

#define FILL_WX(ST, KC)                                                         \
    do {                                                                        \
        int _k0 = (KC) * 16;                                                    \
        _Pragma("unroll")                                                       \
        for (int _i = 0; _i < 2; ++_i) {                                        \
            int _e = tid + _i * 256, _r = _e >> 2, _c = _e & 3;                 \
            uint32_t _d = (uint32_t)__cvta_generic_to_shared(&As[ST][_r][_c*4]);\
            const float* _s = arows[_r] + _k0 + _c * 4;                         \
            int _vb = EMB - (_k0 + _c * 4);                                     \
            int _sz = (_vb >= 4) ? 16 : ((_vb > 0) ? _vb * 4 : 0);              \
            CPA16Z(_d, _s, _sz);                                                \
        }                                                                       \
        _Pragma("unroll")                                                       \
        for (int _i = 0; _i < 2; ++_i) {                                        \
            int _e = tid + _i * 256, _nb = _e >> 5, _ln = _e & 31;              \
            uint32_t _d = (uint32_t)__cvta_generic_to_shared(&Bs[ST][_nb][_ln]);\
            CPA16(_d, g_Bw_f + ((size_t)(nbgBase + _nb) * KCH_E + (KC)) * 32 + _ln); \
        }                                                                       \
        CPCOMMIT();                                                             \
    } while (0)

    FILL_WX(0, 0);
    FILL_WX(1, 1);

    for (int kch = 0; kch < KCH_E; ++kch) {
        const int s = kch % 3;
        if (kch + 1 < KCH_E) { CPWAIT(1); } else { CPWAIT(0); }
        __syncthreads();
        if (kch + 2 < KCH_E) FILL_WX((kch + 2) % 3, kch + 2);

        uint32_t a[2][2][4];
        #pragma unroll
        for (int kb = 0; kb < 2; ++kb)
            #pragma unroll
            for (int mf = 0; mf < 2; ++mf)
                LDSM_A(a[kb][mf], &As[s][0][0], wm + mf * 16, kb);

        #pragma unroll
        for (int nf = 0; nf < 8; ++nf) {
            uint4 bq = Bs[s][nbW + nf][lane];
            #pragma unroll
            for (int mf = 0; mf < 2; ++mf) {
                MMA_STEP(acc[mf][nf], a[0][mf], bq.x, bq.y);
                MMA_STEP(acc[mf][nf], a[1][mf], bq.z, bq.w);
            }
        }
    }
#undef FILL_WX

    #pragma unroll
    for (int mf = 0; mf < 2; ++mf)
        #pragma unroll
        for (int nf = 0; nf < 8; ++nf) {
            int row = rowBase + wm + mf * 16 + tg;
            int col = colBase + wn + nf * 8 + tk * 2;
            if (col < NC) {
                float b0 = g_bias[col], b1 = g_bias[col + 1];
                if (row < NROWS)
                    *(float2*)(g_wx + (size_t)row * NC + col) =
                        make_float2(acc[mf][nf][0] + b0, acc[mf][nf][1] + b1);
                if (row + 8 < NROWS)
                    *(float2*)(g_wx + (size_t)(row + 8) * NC + col) =
                        make_float2(acc[mf][nf][2] + b0, acc[mf][nf][3] + b1);
            }
        }
}

// ---------------------------------------------------------------------------
// level_gemm: fused per-level GEMMs (affine A).
//  blockIdx.y < 8 : IOU: A = g_Hs (M=np*64), B=U_iou, N=900 -> g_Ti
//  blockIdx.y >= 8: F:   A = H children (M=np*128), B=U_f, N=300 -> g_Tf
// ---------------------------------------------------------------------------
__global__ __launch_bounds__(256, 2) void level_gemm(int p0, int np)
{
    extern __shared__ char smem[];
    float (*As)[128][20] = (float (*)[128][20])smem;
    uint4 (*Bs)[16][32]  = (uint4 (*)[16][32])(smem + 3 * 128 * 80);

    const int tid = threadIdx.x;
    const bool isF = (blockIdx.y >= 8);
    const int Mrows = isF ? np * 128 : np * 64;
    const int rowBase = blockIdx.x * 128;
    if (rowBase >= Mrows) return;
    const int colBase = (isF ? (blockIdx.y - 8) : blockIdx.y) * 128;
    const int Nout = isF ? 300 : 900;
    const uint4* gB = isF ? g_Bf_f : g_Bi_f;
    float* Cout = isF ? g_Tf : g_Ti;

    const int lane = tid & 31, warp = tid >> 5;
    const int wm = (warp & 3) * 32, wn = (warp >> 2) * 64;
    const int nbW = wn >> 3;
    const int tg = lane >> 2, tk = lane & 3;
    const int nbgBase = colBase >> 3;

    const int ar = tid >> 1;
    const int ac = (tid & 1) << 1;
    int arow = rowBase + ar; if (arow >= Mrows) arow = Mrows - 1;
    const float* asrc = isF
        ? g_H  + (size_t)((2 * p0 + 1) * B_ + arow) * H_LD
        : g_Hs + (size_t)arow * H_LD;

    float acc[2][8][4] = {};

#define FILL_LV(ST, KC)                                                         \
    do {                                                                        \
        int _k0 = (KC) * 16;                                                    \
        _Pragma("unroll")                                                       \
        for (int _i = 0; _i < 2; ++_i) {                                        \
            int _c = ac + _i;                                                   \
            uint32_t _d = (uint32_t)__cvta_generic_to_shared(&As[ST][ar][_c*4]);\
            CPA16(_d, asrc + _k0 + _c * 4);                                     \
        }                                                                       \
        _Pragma("unroll")                                                       \
        for (int _i = 0; _i < 2; ++_i) {                                        \
            int _e = tid + _i * 256, _nb = _e >> 5, _ln = _e & 31;              \
            uint32_t _d = (uint32_t)__cvta_generic_to_shared(&Bs[ST][_nb][_ln]);\
            CPA16(_d, gB + ((size_t)(nbgBase + _nb) * KCH_U + (KC)) * 32 + _ln);\
        }                                                                       \
        CPCOMMIT();                                                             \
    } while (0)

    FILL_LV(0, 0);
    FILL_LV(1, 1);

    for (int kch = 0; kch < KCH_U; ++kch) {
        const int s = kch % 3;
        if (kch + 1 < KCH_U) { CPWAIT(1); } else { CPWAIT(0); }
        __syncthreads();
        if (kch + 2 < KCH_U) FILL_LV((kch + 2) % 3, kch + 2);

        uint32_t a[2][2][4];
        #pragma unroll
        for (int kb = 0; kb < 2; ++kb)
            #pragma unroll
            for (int mf = 0; mf < 2; ++mf)
                LDSM_A(a[kb][mf], &As[s][0][0], wm + mf * 16, kb);

        #pragma unroll
        for (int nf = 0; nf < 8; ++nf) {
            uint4 bq = Bs[s][nbW + nf][lane];
            #pragma unroll
            for (int mf = 0; mf < 2; ++mf) {
                MMA_STEP(acc[mf][nf], a[0][mf], bq.x, bq.y);
                MMA_STEP(acc[mf][nf], a[1][mf], bq.z, bq.w);
            }
        }
    }
#undef FILL_LV

    #pragma unroll
    for (int mf = 0; mf < 2; ++mf)
        #pragma unroll
        for (int nf = 0; nf < 8; ++nf) {
            int row = rowBase + wm + mf * 16 + tg;
            int col = colBase + wn + nf * 8 + tk * 2;
            if (col < Nout) {
                if (row < Mrows)
                    *(float2*)(Cout + (size_t)row * Nout + col) =
                        make_float2(acc[mf][nf][0], acc[mf][nf][1]);
                if (row + 8 < Mrows)
                    *(float2*)(Cout + (size_t)(row + 8) * Nout + col) =
                        make_float2(acc[mf][nf][2], acc[mf][nf][3]);
            }
        }
}

// ---------------------------------------------------------------------------
// Leaves, sibling-paired: writes H, C for both leaves + Hs row for d=6.
// ---------------------------------------------------------------------------
__global__ void leaf_kernel()
{
    int idx = blockIdx.x * blockDim.x + threadIdx.x;
    if (idx >= 64 * B_ * HID) return;
    int n = idx % HID;
    int r = idx / HID;
    int b = r % B_;
    int j = r / B_;

    float hs = 0.0f;
    #pragma unroll
    for (int s = 0; s < 2; ++s) {
        int node = 127 + 2 * j + s;
        int row  = node * B_ + b;
        const float* wx = g_wx + (size_t)row * NC;
        float iv = sigmoidf(wx[n]);
        float ov = sigmoidf(wx[300 + n]);
        float uv = tanhf(wx[600 + n]);
        float c  = iv * uv;
        float h  = ov * tanhf(c);
        g_C[(size_t)row * HID + n] = c;
        g_H[(size_t)row * H_LD + n] = h;
        hs += h;
    }
    g_Hs[(size_t)r * H_LD + n] = hs;
}

// ---------------------------------------------------------------------------
// Pointwise gates
// ---------------------------------------------------------------------------
__device__ __forceinline__ float node_gate(int p0, int pi, int b, int n, float* cOut)
{
    int p = p0 + pi;
    const float* wx = g_wx + (size_t)(p * B_ + b) * NC;
    const float* ti = g_Ti + (size_t)(pi * B_ + b) * 900;
    float iv = sigmoidf(wx[n]       + ti[n]);
    float ov = sigmoidf(wx[300 + n] + ti[300 + n]);
    float uv = tanhf   (wx[600 + n] + ti[600 + n]);
    float wf = wx[900 + n];
    float fl = sigmoidf(wf + g_Tf[(size_t)((2 * pi    ) * B_ + b) * 300 + n]);
    float fr = sigmoidf(wf + g_Tf[(size_t)((2 * pi + 1) * B_ + b) * 300 + n]);
    int lc = 2 * p + 1, rc = 2 * p + 2;
    float fc = fl * g_C[(size_t)(lc * B_ + b) * HID + n]
             + fr * g_C[(size_t)(rc * B_ + b) * HID + n];
    float c = iv * uv + fc;
    *cOut = c;
    return ov * tanhf(c);
}

__global__ void level_pw_pair(int p0, int np)
{
    int idx = blockIdx.x * blockDim.x + threadIdx.x;
    int tot = (np >> 1) * B_ * HID;
    if (idx >= tot) return;
    int n = idx % HID;
    int r = idx / HID;
    int b = r % B_;
    int i = r / B_;

    float cL, cR;
    float hL = node_gate(p0, 2 * i,     b, n, &cL);
    float hR = node_gate(p0, 2 * i + 1, b, n, &cR);

    int pL = p0 + 2 * i, pR = pL + 1;
    g_C[(size_t)(pL * B_ + b) * HID + n] = cL;
    g_C[(size_t)(pR * B_ + b) * HID + n] = cR;
    g_H[(size_t)(pL * B_ + b) * H_LD + n] = hL;
    g_H[(size_t)(pR * B_ + b) * H_LD + n] = hR;
    g_Hs[(size_t)r * H_LD + n] = hL + hR;
}

__global__ void level_pw_root()
{
    int idx = blockIdx.x * blockDim.x + threadIdx.x;
    if (idx >= B_ * HID) return;
    int n = idx % HID;
    int b = idx / HID;
    float c;
    float h = node_gate(0, 0, b, n, &c);
    g_C[(size_t)b * HID + n] = c;
    g_H[(size_t)b * H_LD + n] = h;
}

// ---------------------------------------------------------------------------
// Output head
// ---------------------------------------------------------------------------
__global__ __launch_bounds__(64) void out_kernel(
    const float* __restrict__ W_out, const float* __restrict__ b_out,
    float* __restrict__ out)
{
    const int b = threadIdx.x;
    const float* h = g_H + (size_t)b * H_LD;
    float l0 = b_out[0], l1 = b_out[1];
    #pragma unroll 4
    for (int k = 0; k < HID; ++k) {
        float hv = h[k];
        l0 = fmaf(hv, W_out[k * 2 + 0], l0);
        l1 = fmaf(hv, W_out[k * 2 + 1], l1);
    }
    float m   = fmaxf(l0, l1);
    float lse = m + logf(expf(l0 - m) + expf(l1 - m));
    out[b * 2 + 0] = l0 - lse;
    out[b * 2 + 1] = l1 - lse;
}

// ---------------------------------------------------------------------------
extern "C" void kernel_launch(void* const* d_in, const int* in_sizes, int n_in,
                              void* d_out, int out_size)
{
    (void)in_sizes; (void)n_in; (void)out_size;
    const int*   x     = (const int*)  d_in[0];
    const float* embed = (const float*)d_in[3];
    const float* W_iou = (const float*)d_in[4];
    const float* U_iou = (const float*)d_in[5];
    const float* b_iou = (const float*)d_in[6];
    const float* W_f   = (const float*)d_in[7];
    const float* U_f   = (const float*)d_in[8];
    const float* b_f   = (const float*)d_in[9];
    const float* W_out = (const float*)d_in[10];
    const float* b_out = (const float*)d_in[11];

    const int SMEM_WX = 3 * 128 * 80 + 3 * 16 * 32 * 16 + 128 * 8;
    const int SMEM_LV = 3 * 128 * 80 + 3 * 16 * 32 * 16;
    cudaFuncSetAttribute(gemm_wx,    cudaFuncAttributeMaxDynamicSharedMemorySize, SMEM_WX);
    cudaFuncSetAttribute(level_gemm, cudaFuncAttributeMaxDynamicSharedMemorySize, SMEM_LV);

    prep_kernel<<<(NBGI * KCH_U * 32 + 255) / 256, 256>>>(W_iou, W_f, U_iou, U_f, b_iou, b_f);

    gemm_wx<<<dim3(128, 10), 256, SMEM_WX>>>(embed, x);
    leaf_kernel<<<(64 * B_ * HID + 255) / 256, 256>>>();

    for (int d = 6; d >= 1; --d) {
        int np = 1 << d;
        int p0 = np - 1;
        level_gemm<<<dim3(np, 11), 256, SMEM_LV>>>(p0, np);
        level_pw_pair<<<((np / 2) * B_ * HID + 255) / 256, 256>>>(p0, np);
    }
    level_gemm<<<dim3(1, 11), 256, SMEM_LV>>>(0, 1);
    level_pw_root<<<(B_ * HID + 255) / 256, 256>>>();

    out_kernel<<<1, 64>>>(W_out, b_out, (float*)d_out);
}